// round 6
// baseline (speedup 1.0000x reference)
#include <cuda_runtime.h>
#include <cuda_bf16.h>
#include <cstdint>

#define DEV_INLINE __device__ __forceinline__

// ---------------------------------------------------------------------------
// out[16384,4096] = x[16384,1024] @ (W + w1[s]@w2[t])^T + bias
//
// fp32 emulated via bf16 hi/lo split, THREE-TERM scheme (Ootomo):
//   x = xh + xl,  w = wh + wl  (bf16 each)
//   out ~= xh.wh + xh.wl + xl.wh      (xl.wl ~ 2^-16 relative, dropped)
// Storage stays packed: A = [xh | xl] (M x 2048), B = [wh | wl] (N x 2048).
// The GEMM runs 96 BK=32 stages in 3 phases, picking (ka, kb) offsets
// independently per operand so all three products hit the same accumulators.
//
// NOTE: tcgen05 unavailable (harness PTX targets base sm_103, no 'a' suffix);
// using arch-neutral mma.sync (HMMA) + ldmatrix + cp.async.
// ---------------------------------------------------------------------------
constexpr int Mdim = 16384;
constexpr int Ndim = 4096;
constexpr int Kdim = 1024;
constexpr int KP   = 2048;          // packed storage K' (hi | lo)
constexpr int RANKC = 32;
constexpr int NLANG_OUT = 4096;

constexpr int BM = 128, BN = 128, BK = 32;
constexpr int KT = 3 * (Kdim / BK);  // 96 k-stages: 3 phases x 32
constexpr int STAGES = 4;
constexpr int ROW_BYTES = BK * 2;    // 64 B per tile row
constexpr int TILE_BYTES = BM * ROW_BYTES;       // 8 KB
constexpr int STAGE_BYTES = 2 * TILE_BYTES;      // A + B = 16 KB
constexpr int SMEM_BYTES = STAGES * STAGE_BYTES; // 64 KB

// Scratch (no cudaMalloc allowed)
__device__ __nv_bfloat16 g_a[(size_t)Mdim * KP];   // 64 MB
__device__ __nv_bfloat16 g_b[(size_t)Ndim * KP];   // 16 MB

// ---------------------------------------------------------------------------
// helpers
// ---------------------------------------------------------------------------
DEV_INLINE uint32_t smem_to_u32(const void* p) {
    uint32_t a;
    asm("{ .reg .u64 t; cvta.to.shared.u64 t, %1; cvt.u32.u64 %0, t; }" : "=r"(a) : "l"(p));
    return a;
}

DEV_INLINE void cp_async16(uint32_t dst, const void* src) {
    asm volatile("cp.async.cg.shared.global [%0], [%1], 16;" :: "r"(dst), "l"(src) : "memory");
}
DEV_INLINE void cp_commit() { asm volatile("cp.async.commit_group;" ::: "memory"); }
template <int N> DEV_INLINE void cp_wait() {
    asm volatile("cp.async.wait_group %0;" :: "n"(N) : "memory");
}

DEV_INLINE void ldsm_x4(uint32_t& r0, uint32_t& r1, uint32_t& r2, uint32_t& r3, uint32_t addr) {
    asm volatile("ldmatrix.sync.aligned.m8n8.x4.shared.b16 {%0,%1,%2,%3}, [%4];"
                 : "=r"(r0), "=r"(r1), "=r"(r2), "=r"(r3) : "r"(addr));
}

DEV_INLINE void mma_bf16(float& c0, float& c1, float& c2, float& c3,
                         uint32_t a0, uint32_t a1, uint32_t a2, uint32_t a3,
                         uint32_t b0, uint32_t b1) {
    asm volatile(
        "mma.sync.aligned.m16n8k16.row.col.f32.bf16.bf16.f32 "
        "{%0,%1,%2,%3}, {%4,%5,%6,%7}, {%8,%9}, {%0,%1,%2,%3};"
        : "+f"(c0), "+f"(c1), "+f"(c2), "+f"(c3)
        : "r"(a0), "r"(a1), "r"(a2), "r"(a3), "r"(b0), "r"(b1));
}

// XOR swizzle on 16B chunks: row stride 64B (4 chunks); phys chunk = c ^ ((row>>1)&3).
// Conflict-free for ldmatrix reading 8 consecutive rows at a fixed logical chunk.
DEV_INLINE uint32_t swz(int row, int chunk) {
    return (uint32_t)(row * ROW_BYTES + ((chunk ^ ((row >> 1) & 3)) << 4));
}

// Per-stage K offsets for the 3-term scheme.
// phase 0: xh.wh   phase 1: xh.wl   phase 2: xl.wh
DEV_INLINE void stage_k(int s, int& ka, int& kb) {
    const int sk = (s & 31) * BK;       // 0..992 within the 1024-wide half
    const int ph = s >> 5;              // 0,1,2
    ka = (ph == 2 ? Kdim : 0) + sk;
    kb = (ph == 1 ? Kdim : 0) + sk;
}

// ---------------------------------------------------------------------------
// Prep: split fp32 -> bf16 hi/lo, packed [hi(0..1023) | lo(1024..2047)] per row
// ---------------------------------------------------------------------------
DEV_INLINE void split_bf16(float v, __nv_bfloat16& h, __nv_bfloat16& l) {
    h = __float2bfloat16(v);
    l = __float2bfloat16(v - __bfloat162float(h));
}

__global__ void prep_x_kernel(const float4* __restrict__ x4) {
    const size_t i = (size_t)blockIdx.x * blockDim.x + threadIdx.x;   // < M*K/4
    const size_t row = i >> 8;                 // K/4 = 256 float4 per row
    const int    col = (int)(i & 255) << 2;    // 0..1020
    const float4 v = x4[i];
    __nv_bfloat16 h0, l0, h1, l1, h2, l2, h3, l3;
    split_bf16(v.x, h0, l0); split_bf16(v.y, h1, l1);
    split_bf16(v.z, h2, l2); split_bf16(v.w, h3, l3);
    __nv_bfloat162* p = reinterpret_cast<__nv_bfloat162*>(g_a + row * KP + col);
    p[0] = __halves2bfloat162(h0, h1);
    p[1] = __halves2bfloat162(h2, h3);
    __nv_bfloat162* q = reinterpret_cast<__nv_bfloat162*>(g_a + row * KP + Kdim + col);
    q[0] = __halves2bfloat162(l0, l1);
    q[1] = __halves2bfloat162(l2, l3);
}

__global__ void prep_w_kernel(const float* __restrict__ weight,
                              const float* __restrict__ w1,
                              const float* __restrict__ w2,
                              const int* __restrict__ src_id,
                              const int* __restrict__ tgt_id) {
    __shared__ float a[RANKC];
    const int o = blockIdx.x;
    const int tid = threadIdx.x;
    if (tid < RANKC)
        a[tid] = w1[((size_t)src_id[0] * NLANG_OUT + o) * RANKC + tid];
    __syncthreads();
    const int t = tgt_id[0];

    const int i0 = tid * 4;   // 256 threads * 4 = 1024
    float4 acc = *reinterpret_cast<const float4*>(weight + (size_t)o * Kdim + i0);
#pragma unroll
    for (int r = 0; r < RANKC; ++r) {
        const float4 b = *reinterpret_cast<const float4*>(w2 + ((size_t)t * RANKC + r) * Kdim + i0);
        const float ar = a[r];
        acc.x = fmaf(ar, b.x, acc.x);
        acc.y = fmaf(ar, b.y, acc.y);
        acc.z = fmaf(ar, b.z, acc.z);
        acc.w = fmaf(ar, b.w, acc.w);
    }
    __nv_bfloat16 h0, l0, h1, l1, h2, l2, h3, l3;
    split_bf16(acc.x, h0, l0); split_bf16(acc.y, h1, l1);
    split_bf16(acc.z, h2, l2); split_bf16(acc.w, h3, l3);
    __nv_bfloat162* p = reinterpret_cast<__nv_bfloat162*>(g_b + (size_t)o * KP + i0);
    p[0] = __halves2bfloat162(h0, h1);
    p[1] = __halves2bfloat162(h2, h3);
    __nv_bfloat162* q = reinterpret_cast<__nv_bfloat162*>(g_b + (size_t)o * KP + Kdim + i0);
    q[0] = __halves2bfloat162(l0, l1);
    q[1] = __halves2bfloat162(l2, l3);
}

// ---------------------------------------------------------------------------
// GEMM: 128x128 CTA tile, 8 warps (4 M x 2 N), warp tile 32x64, BK=32,
// 4-stage cp.async pipeline, ldmatrix + mma.sync bf16, 96 stages (3 phases)
// ---------------------------------------------------------------------------
__global__ void __launch_bounds__(256, 2)
gemm_kernel(float* __restrict__ out, const float* __restrict__ bias) {
    extern __shared__ char smem[];
    const uint32_t smem_base = smem_to_u32(smem);
    const int tid  = threadIdx.x;
    const int lane = tid & 31;
    const int wid  = tid >> 5;
    const int warp_m = wid & 3;     // 4 warps in M -> 32 rows each
    const int warp_n = wid >> 2;    // 2 warps in N -> 64 cols each
    const int n0 = blockIdx.x * BN; // n fastest: W-panel reuse in L2
    const int m0 = blockIdx.y * BM;

    // ---- cp.async per-thread mapping (2 chunks each for A and B) ----
    uint32_t st_dst[2];
    const __nv_bfloat16* srcA[2];
    const __nv_bfloat16* srcB[2];
#pragma unroll
    for (int j = 0; j < 2; ++j) {
        const int cid = tid * 2 + j;       // 0..511
        const int row = cid >> 2;          // 0..127
        const int ch  = cid & 3;
        st_dst[j] = swz(row, ch);
        srcA[j] = g_a + (size_t)(m0 + row) * KP + ch * 8;
        srcB[j] = g_b + (size_t)(n0 + row) * KP + ch * 8;
    }

    // ---- ldmatrix per-thread smem offsets (constant across stages) ----
    const int g  = lane >> 3;
    const int lr = lane & 7;
    uint32_t offA[2][2];   // [mt][kk]
#pragma unroll
    for (int mt = 0; mt < 2; ++mt)
#pragma unroll
        for (int kk = 0; kk < 2; ++kk) {
            const int row = warp_m * 32 + mt * 16 + (g & 1) * 8 + lr;
            offA[mt][kk] = swz(row, 2 * kk + (g >> 1));
        }
    uint32_t offB[4][2];   // [np][kk] ; np covers n-tiles 2np, 2np+1
#pragma unroll
    for (int np = 0; np < 4; ++np)
#pragma unroll
        for (int kk = 0; kk < 2; ++kk) {
            const int row = warp_n * 64 + np * 16 + (g >> 1) * 8 + lr;
            offB[np][kk] = swz(row, 2 * kk + (g & 1));
        }

    float acc[2][8][4];
#pragma unroll
    for (int mt = 0; mt < 2; ++mt)
#pragma unroll
        for (int nt = 0; nt < 8; ++nt)
#pragma unroll
            for (int c = 0; c < 4; ++c) acc[mt][nt][c] = 0.f;

    // ---- prologue: stages 0..2 ----
#pragma unroll
    for (int s = 0; s < STAGES - 1; ++s) {
        const uint32_t sa = smem_base + s * STAGE_BYTES;
        const uint32_t sb = sa + TILE_BYTES;
        int ka, kb; stage_k(s, ka, kb);
#pragma unroll
        for (int j = 0; j < 2; ++j) {
            cp_async16(sa + st_dst[j], srcA[j] + ka);
            cp_async16(sb + st_dst[j], srcB[j] + kb);
        }
        cp_commit();
    }

    // ---- mainloop: 96 stages, 3 phases sharing the same accumulators ----
#pragma unroll 1
    for (int s = 0; s < KT; ++s) {
        cp_wait<STAGES - 2>();
        __syncthreads();

        // prefetch stage s+3
        if (s + STAGES - 1 < KT) {
            const uint32_t sa = smem_base + ((s + STAGES - 1) & (STAGES - 1)) * STAGE_BYTES;
            const uint32_t sb = sa + TILE_BYTES;
            int ka, kb; stage_k(s + STAGES - 1, ka, kb);
#pragma unroll
            for (int j = 0; j < 2; ++j) {
                cp_async16(sa + st_dst[j], srcA[j] + ka);
                cp_async16(sb + st_dst[j], srcB[j] + kb);
            }
        }
        cp_commit();   // commit every iter (possibly empty) to keep group count fixed

        const uint32_t sa = smem_base + (s & (STAGES - 1)) * STAGE_BYTES;
        const uint32_t sb = sa + TILE_BYTES;
#pragma unroll
        for (int kk = 0; kk < 2; ++kk) {
            uint32_t a[2][4];
#pragma unroll
            for (int mt = 0; mt < 2; ++mt)
                ldsm_x4(a[mt][0], a[mt][1], a[mt][2], a[mt][3], sa + offA[mt][kk]);
            uint32_t b[8][2];
#pragma unroll
            for (int np = 0; np < 4; ++np) {
                uint32_t r0, r1, r2, r3;
                ldsm_x4(r0, r1, r2, r3, sb + offB[np][kk]);
                b[2 * np][0] = r0; b[2 * np][1] = r1;
                b[2 * np + 1][0] = r2; b[2 * np + 1][1] = r3;
            }
#pragma unroll
            for (int mt = 0; mt < 2; ++mt)
#pragma unroll
                for (int nt = 0; nt < 8; ++nt)
                    mma_bf16(acc[mt][nt][0], acc[mt][nt][1], acc[mt][nt][2], acc[mt][nt][3],
                             a[mt][0], a[mt][1], a[mt][2], a[mt][3],
                             b[nt][0], b[nt][1]);
        }
    }

    // ---- epilogue ----
    const int qid = lane >> 2;     // row 0..7 within m8
    const int qln = lane & 3;      // col pair
    const int nbase = n0 + warp_n * 64;
    float2 bv[8];
#pragma unroll
    for (int nt = 0; nt < 8; ++nt)
        bv[nt] = *reinterpret_cast<const float2*>(bias + nbase + nt * 8 + qln * 2);

#pragma unroll
    for (int mt = 0; mt < 2; ++mt) {
#pragma unroll
        for (int rr = 0; rr < 2; ++rr) {
            const int m = m0 + warp_m * 32 + mt * 16 + rr * 8 + qid;
            float* orow = out + (size_t)m * Ndim + nbase;
#pragma unroll
            for (int nt = 0; nt < 8; ++nt) {
                float2 v;
                v.x = acc[mt][nt][rr * 2 + 0] + bv[nt].x;
                v.y = acc[mt][nt][rr * 2 + 1] + bv[nt].y;
                *reinterpret_cast<float2*>(orow + nt * 8 + qln * 2) = v;
            }
        }
    }
}

// ---------------------------------------------------------------------------
// Launch
// ---------------------------------------------------------------------------
extern "C" void kernel_launch(void* const* d_in, const int* in_sizes, int n_in,
                              void* d_out, int out_size) {
    const float* x      = (const float*)d_in[0];   // [4,4096,1024]
    const float* weight = (const float*)d_in[1];   // [4096,1024]
    const float* bias   = (const float*)d_in[2];   // [4096]
    const float* w1     = (const float*)d_in[3];   // [9,4096,32]
    const float* w2     = (const float*)d_in[4];   // [9,32,1024]
    const int*   src_id = (const int*)d_in[5];
    const int*   tgt_id = (const int*)d_in[6];
    float* out = (float*)d_out;
    (void)in_sizes; (void)n_in; (void)out_size;

    cudaFuncSetAttribute(gemm_kernel, cudaFuncAttributeMaxDynamicSharedMemorySize, SMEM_BYTES);

    prep_w_kernel<<<Ndim, 256>>>(weight, w1, w2, src_id, tgt_id);
    prep_x_kernel<<<(Mdim * Kdim / 4) / 256, 256>>>(reinterpret_cast<const float4*>(x));

    dim3 grid(Ndim / BN, Mdim / BM);   // (32, 128), n fastest
    gemm_kernel<<<grid, 256, SMEM_BYTES>>>(out, bias);
}

// round 7
// speedup vs baseline: 2.4157x; 2.4157x over previous
#include <cuda_runtime.h>
#include <cuda_fp16.h>
#include <cstdint>

#define DEV_INLINE __device__ __forceinline__

// ---------------------------------------------------------------------------
// out[16384,4096] = x[16384,1024] @ (W + w1[s]@w2[t])^T + bias
//
// Single fp16 GEMM. Error model (validated R5/R6): computing in fp16 drops
// only input-rounding terms x.w.(eps_x+eps_w); fp16 x fp16 products are EXACT
// in the fp32 accumulator (22 <= 24 mantissa bits). Measured bf16 cross-term
// error was 2.35e-3; fp16 has exactly 3 more mantissa bits ->
// predicted rel_err = 2.35e-3 / 8 = 2.9e-4  (threshold 1e-3, fixed inputs).
//
// NOTE: tcgen05 unavailable (harness PTX targets base sm_103, no 'a' suffix);
// using arch-neutral mma.sync (HMMA) + ldmatrix + cp.async.
// ---------------------------------------------------------------------------
constexpr int Mdim = 16384;
constexpr int Ndim = 4096;
constexpr int Kdim = 1024;
constexpr int RANKC = 32;
constexpr int NLANG_OUT = 4096;

constexpr int BM = 128, BN = 128, BK = 32;
constexpr int KT = Kdim / BK;        // 32 k-stages
constexpr int STAGES = 6;
constexpr int ROW_BYTES = BK * 2;    // 64 B per tile row
constexpr int TILE_BYTES = BM * ROW_BYTES;       // 8 KB
constexpr int STAGE_BYTES = 2 * TILE_BYTES;      // A + B = 16 KB
constexpr int SMEM_BYTES = STAGES * STAGE_BYTES; // 96 KB

// Scratch (no cudaMalloc allowed): fp16 copies of x and w_eff
__device__ __half g_a[(size_t)Mdim * Kdim];   // 32 MB
__device__ __half g_b[(size_t)Ndim * Kdim];   // 8 MB

// ---------------------------------------------------------------------------
// helpers
// ---------------------------------------------------------------------------
DEV_INLINE uint32_t smem_to_u32(const void* p) {
    uint32_t a;
    asm("{ .reg .u64 t; cvta.to.shared.u64 t, %1; cvt.u32.u64 %0, t; }" : "=r"(a) : "l"(p));
    return a;
}

DEV_INLINE void cp_async16(uint32_t dst, const void* src) {
    asm volatile("cp.async.cg.shared.global [%0], [%1], 16;" :: "r"(dst), "l"(src) : "memory");
}
DEV_INLINE void cp_commit() { asm volatile("cp.async.commit_group;" ::: "memory"); }
template <int N> DEV_INLINE void cp_wait() {
    asm volatile("cp.async.wait_group %0;" :: "n"(N) : "memory");
}

DEV_INLINE void ldsm_x4(uint32_t& r0, uint32_t& r1, uint32_t& r2, uint32_t& r3, uint32_t addr) {
    asm volatile("ldmatrix.sync.aligned.m8n8.x4.shared.b16 {%0,%1,%2,%3}, [%4];"
                 : "=r"(r0), "=r"(r1), "=r"(r2), "=r"(r3) : "r"(addr));
}

DEV_INLINE void mma_f16(float& c0, float& c1, float& c2, float& c3,
                        uint32_t a0, uint32_t a1, uint32_t a2, uint32_t a3,
                        uint32_t b0, uint32_t b1) {
    asm volatile(
        "mma.sync.aligned.m16n8k16.row.col.f32.f16.f16.f32 "
        "{%0,%1,%2,%3}, {%4,%5,%6,%7}, {%8,%9}, {%0,%1,%2,%3};"
        : "+f"(c0), "+f"(c1), "+f"(c2), "+f"(c3)
        : "r"(a0), "r"(a1), "r"(a2), "r"(a3), "r"(b0), "r"(b1));
}

// XOR swizzle on 16B chunks: row stride 64B (4 chunks); phys chunk = c ^ ((row>>1)&3).
// Conflict-free for ldmatrix reading 8 consecutive rows at a fixed logical chunk.
DEV_INLINE uint32_t swz(int row, int chunk) {
    return (uint32_t)(row * ROW_BYTES + ((chunk ^ ((row >> 1) & 3)) << 4));
}

// ---------------------------------------------------------------------------
// Prep kernels: fp32 -> fp16 (round-to-nearest)
// ---------------------------------------------------------------------------
__global__ void prep_x_kernel(const float4* __restrict__ x4) {
    const size_t i = (size_t)blockIdx.x * blockDim.x + threadIdx.x;   // < M*K/4
    const float4 v = x4[i];
    __half2* p = reinterpret_cast<__half2*>(g_a + 4 * i);   // row*K + col == 4*i
    p[0] = __floats2half2_rn(v.x, v.y);
    p[1] = __floats2half2_rn(v.z, v.w);
}

__global__ void prep_w_kernel(const float* __restrict__ weight,
                              const float* __restrict__ w1,
                              const float* __restrict__ w2,
                              const int* __restrict__ src_id,
                              const int* __restrict__ tgt_id) {
    __shared__ float a[RANKC];
    const int o = blockIdx.x;
    const int tid = threadIdx.x;
    if (tid < RANKC)
        a[tid] = w1[((size_t)src_id[0] * NLANG_OUT + o) * RANKC + tid];
    __syncthreads();
    const int t = tgt_id[0];

    const int i0 = tid * 4;   // 256 threads * 4 = 1024
    float4 acc = *reinterpret_cast<const float4*>(weight + (size_t)o * Kdim + i0);
#pragma unroll
    for (int r = 0; r < RANKC; ++r) {
        const float4 b = *reinterpret_cast<const float4*>(w2 + ((size_t)t * RANKC + r) * Kdim + i0);
        const float ar = a[r];
        acc.x = fmaf(ar, b.x, acc.x);
        acc.y = fmaf(ar, b.y, acc.y);
        acc.z = fmaf(ar, b.z, acc.z);
        acc.w = fmaf(ar, b.w, acc.w);
    }
    __half2* p = reinterpret_cast<__half2*>(g_b + (size_t)o * Kdim + i0);
    p[0] = __floats2half2_rn(acc.x, acc.y);
    p[1] = __floats2half2_rn(acc.z, acc.w);
}

// ---------------------------------------------------------------------------
// GEMM: 128x128 CTA tile, 8 warps (4 M x 2 N), warp tile 32x64, BK=32,
// 6-stage cp.async pipeline, ldmatrix + mma.sync fp16
// ---------------------------------------------------------------------------
__global__ void __launch_bounds__(256, 2)
gemm_kernel(float* __restrict__ out, const float* __restrict__ bias) {
    extern __shared__ char smem[];
    const uint32_t smem_base = smem_to_u32(smem);
    const int tid  = threadIdx.x;
    const int lane = tid & 31;
    const int wid  = tid >> 5;
    const int warp_m = wid & 3;     // 4 warps in M -> 32 rows each
    const int warp_n = wid >> 2;    // 2 warps in N -> 64 cols each
    const int n0 = blockIdx.x * BN; // n fastest: W-panel reuse in L2
    const int m0 = blockIdx.y * BM;

    // ---- cp.async per-thread mapping (2 chunks each for A and B) ----
    uint32_t st_dst[2];
    const __half* srcA[2];
    const __half* srcB[2];
#pragma unroll
    for (int j = 0; j < 2; ++j) {
        const int cid = tid * 2 + j;       // 0..511
        const int row = cid >> 2;          // 0..127
        const int ch  = cid & 3;
        st_dst[j] = swz(row, ch);
        srcA[j] = g_a + (size_t)(m0 + row) * Kdim + ch * 8;
        srcB[j] = g_b + (size_t)(n0 + row) * Kdim + ch * 8;
    }

    // ---- ldmatrix per-thread smem offsets (constant across stages) ----
    const int g  = lane >> 3;
    const int lr = lane & 7;
    uint32_t offA[2][2];   // [mt][kk]
#pragma unroll
    for (int mt = 0; mt < 2; ++mt)
#pragma unroll
        for (int kk = 0; kk < 2; ++kk) {
            const int row = warp_m * 32 + mt * 16 + (g & 1) * 8 + lr;
            offA[mt][kk] = swz(row, 2 * kk + (g >> 1));
        }
    uint32_t offB[4][2];   // [np][kk] ; np covers n-tiles 2np, 2np+1
#pragma unroll
    for (int np = 0; np < 4; ++np)
#pragma unroll
        for (int kk = 0; kk < 2; ++kk) {
            const int row = warp_n * 64 + np * 16 + (g >> 1) * 8 + lr;
            offB[np][kk] = swz(row, 2 * kk + (g & 1));
        }

    float acc[2][8][4];
#pragma unroll
    for (int mt = 0; mt < 2; ++mt)
#pragma unroll
        for (int nt = 0; nt < 8; ++nt)
#pragma unroll
            for (int c = 0; c < 4; ++c) acc[mt][nt][c] = 0.f;

    // ---- prologue: stages 0..STAGES-2 ----
#pragma unroll
    for (int s = 0; s < STAGES - 1; ++s) {
        const uint32_t sa = smem_base + s * STAGE_BYTES;
        const uint32_t sb = sa + TILE_BYTES;
        const int k0 = s * BK;
#pragma unroll
        for (int j = 0; j < 2; ++j) {
            cp_async16(sa + st_dst[j], srcA[j] + k0);
            cp_async16(sb + st_dst[j], srcB[j] + k0);
        }
        cp_commit();
    }

    // ---- mainloop ----
    int ld_stage = STAGES - 1;   // next stage slot to fill
    int cp_stage = 0;            // stage slot to compute from
#pragma unroll 1
    for (int s = 0; s < KT; ++s) {
        cp_wait<STAGES - 2>();
        __syncthreads();

        // prefetch stage s+STAGES-1
        if (s + STAGES - 1 < KT) {
            const uint32_t sa = smem_base + ld_stage * STAGE_BYTES;
            const uint32_t sb = sa + TILE_BYTES;
            const int k0 = (s + STAGES - 1) * BK;
#pragma unroll
            for (int j = 0; j < 2; ++j) {
                cp_async16(sa + st_dst[j], srcA[j] + k0);
                cp_async16(sb + st_dst[j], srcB[j] + k0);
            }
        }
        cp_commit();   // commit every iter (possibly empty) to keep group count fixed
        if (++ld_stage == STAGES) ld_stage = 0;

        const uint32_t sa = smem_base + cp_stage * STAGE_BYTES;
        const uint32_t sb = sa + TILE_BYTES;
        if (++cp_stage == STAGES) cp_stage = 0;
#pragma unroll
        for (int kk = 0; kk < 2; ++kk) {
            uint32_t a[2][4];
#pragma unroll
            for (int mt = 0; mt < 2; ++mt)
                ldsm_x4(a[mt][0], a[mt][1], a[mt][2], a[mt][3], sa + offA[mt][kk]);
            uint32_t b[8][2];
#pragma unroll
            for (int np = 0; np < 4; ++np) {
                uint32_t r0, r1, r2, r3;
                ldsm_x4(r0, r1, r2, r3, sb + offB[np][kk]);
                b[2 * np][0] = r0; b[2 * np][1] = r1;
                b[2 * np + 1][0] = r2; b[2 * np + 1][1] = r3;
            }
#pragma unroll
            for (int mt = 0; mt < 2; ++mt)
#pragma unroll
                for (int nt = 0; nt < 8; ++nt)
                    mma_f16(acc[mt][nt][0], acc[mt][nt][1], acc[mt][nt][2], acc[mt][nt][3],
                            a[mt][0], a[mt][1], a[mt][2], a[mt][3],
                            b[nt][0], b[nt][1]);
        }
    }

    // ---- epilogue ----
    const int qid = lane >> 2;     // row 0..7 within m8
    const int qln = lane & 3;      // col pair
    const int nbase = n0 + warp_n * 64;
    float2 bv[8];
#pragma unroll
    for (int nt = 0; nt < 8; ++nt)
        bv[nt] = *reinterpret_cast<const float2*>(bias + nbase + nt * 8 + qln * 2);

#pragma unroll
    for (int mt = 0; mt < 2; ++mt) {
#pragma unroll
        for (int rr = 0; rr < 2; ++rr) {
            const int m = m0 + warp_m * 32 + mt * 16 + rr * 8 + qid;
            float* orow = out + (size_t)m * Ndim + nbase;
#pragma unroll
            for (int nt = 0; nt < 8; ++nt) {
                float2 v;
                v.x = acc[mt][nt][rr * 2 + 0] + bv[nt].x;
                v.y = acc[mt][nt][rr * 2 + 1] + bv[nt].y;
                *reinterpret_cast<float2*>(orow + nt * 8 + qln * 2) = v;
            }
        }
    }
}

// ---------------------------------------------------------------------------
// Launch
// ---------------------------------------------------------------------------
extern "C" void kernel_launch(void* const* d_in, const int* in_sizes, int n_in,
                              void* d_out, int out_size) {
    const float* x      = (const float*)d_in[0];   // [4,4096,1024]
    const float* weight = (const float*)d_in[1];   // [4096,1024]
    const float* bias   = (const float*)d_in[2];   // [4096]
    const float* w1     = (const float*)d_in[3];   // [9,4096,32]
    const float* w2     = (const float*)d_in[4];   // [9,32,1024]
    const int*   src_id = (const int*)d_in[5];
    const int*   tgt_id = (const int*)d_in[6];
    float* out = (float*)d_out;
    (void)in_sizes; (void)n_in; (void)out_size;

    cudaFuncSetAttribute(gemm_kernel, cudaFuncAttributeMaxDynamicSharedMemorySize, SMEM_BYTES);

    prep_w_kernel<<<Ndim, 256>>>(weight, w1, w2, src_id, tgt_id);
    prep_x_kernel<<<(Mdim * Kdim / 4) / 256, 256>>>(reinterpret_cast<const float4*>(x));

    dim3 grid(Ndim / BN, Mdim / BM);   // (32, 128), n fastest
    gemm_kernel<<<grid, 256, SMEM_BYTES>>>(out, bias);
}

// round 9
// speedup vs baseline: 3.3194x; 1.3741x over previous
#include <cuda_runtime.h>
#include <cuda_fp16.h>
#include <cstdint>

#define DEV_INLINE __device__ __forceinline__

// ---------------------------------------------------------------------------
// out[16384,4096] = x[16384,1024] @ (W + w1[s]@w2[t])^T + bias
//
// Single fp16 GEMM (validated R7: rel_err 2.94e-4 vs 1e-3 threshold).
// fp16 x fp16 products are exact in fp32 accum; only input rounding remains.
//
// R8 changes vs R7 (487.9 us):
//  - BK=64 stages (16 mainloop iters instead of 32) with STAGES=3 (same 96 KB
//    smem): halves cp.async.wait + __syncthreads count per CTA.
//  - Full 128B-row XOR swizzle (chunk ^ (row&7)), conflict-free per ldmatrix
//    8-lane phase.
//  - prep_w and prep_x fused into ONE launch (block-range split) to overlap.
//
// NOTE: tcgen05 unavailable (harness PTX targets base sm_103, no 'a' suffix);
// using arch-neutral mma.sync (HMMA) + ldmatrix + cp.async.
// ---------------------------------------------------------------------------
constexpr int Mdim = 16384;
constexpr int Ndim = 4096;
constexpr int Kdim = 1024;
constexpr int RANKC = 32;
constexpr int NLANG_OUT = 4096;

constexpr int BM = 128, BN = 128, BK = 64;
constexpr int KT = Kdim / BK;        // 16 k-stages
constexpr int STAGES = 3;
constexpr int ROW_BYTES = BK * 2;    // 128 B per tile row
constexpr int TILE_BYTES = BM * ROW_BYTES;       // 16 KB
constexpr int STAGE_BYTES = 2 * TILE_BYTES;      // A + B = 32 KB
constexpr int SMEM_BYTES = STAGES * STAGE_BYTES; // 96 KB

// Scratch (no cudaMalloc allowed): fp16 copies of x and w_eff
__device__ __half g_a[(size_t)Mdim * Kdim];   // 32 MB
__device__ __half g_b[(size_t)Ndim * Kdim];   // 8 MB

// ---------------------------------------------------------------------------
// helpers
// ---------------------------------------------------------------------------
DEV_INLINE uint32_t smem_to_u32(const void* p) {
    uint32_t a;
    asm("{ .reg .u64 t; cvta.to.shared.u64 t, %1; cvt.u32.u64 %0, t; }" : "=r"(a) : "l"(p));
    return a;
}

DEV_INLINE void cp_async16(uint32_t dst, const void* src) {
    asm volatile("cp.async.cg.shared.global [%0], [%1], 16;" :: "r"(dst), "l"(src) : "memory");
}
DEV_INLINE void cp_commit() { asm volatile("cp.async.commit_group;" ::: "memory"); }
template <int N> DEV_INLINE void cp_wait() {
    asm volatile("cp.async.wait_group %0;" :: "n"(N) : "memory");
}

DEV_INLINE void ldsm_x4(uint32_t& r0, uint32_t& r1, uint32_t& r2, uint32_t& r3, uint32_t addr) {
    asm volatile("ldmatrix.sync.aligned.m8n8.x4.shared.b16 {%0,%1,%2,%3}, [%4];"
                 : "=r"(r0), "=r"(r1), "=r"(r2), "=r"(r3) : "r"(addr));
}

DEV_INLINE void mma_f16(float& c0, float& c1, float& c2, float& c3,
                        uint32_t a0, uint32_t a1, uint32_t a2, uint32_t a3,
                        uint32_t b0, uint32_t b1) {
    asm volatile(
        "mma.sync.aligned.m16n8k16.row.col.f32.f16.f16.f32 "
        "{%0,%1,%2,%3}, {%4,%5,%6,%7}, {%8,%9}, {%0,%1,%2,%3};"
        : "+f"(c0), "+f"(c1), "+f"(c2), "+f"(c3)
        : "r"(a0), "r"(a1), "r"(a2), "r"(a3), "r"(b0), "r"(b1));
}

// Full 128B-row XOR swizzle on 16B chunks: 8 chunks/row, phys = c ^ (row & 7).
// ldmatrix reads 8 consecutive rows at one logical chunk -> 8 distinct phys
// chunks -> conflict-free within each 8-lane ldmatrix phase.
DEV_INLINE uint32_t swz(int row, int chunk) {
    return (uint32_t)(row * ROW_BYTES + ((chunk ^ (row & 7)) << 4));
}

// ---------------------------------------------------------------------------
// Fused prep: blocks [0,4096) build w_eff fp16; blocks [4096,20480) cast x.
// ---------------------------------------------------------------------------
__global__ void prep_kernel(const float4* __restrict__ x4,
                            const float* __restrict__ weight,
                            const float* __restrict__ w1,
                            const float* __restrict__ w2,
                            const int* __restrict__ src_id,
                            const int* __restrict__ tgt_id) {
    const int tid = threadIdx.x;
    if (blockIdx.x < (unsigned)Ndim) {
        // ---- w_eff row o = weight[o] + w1[src][o] @ w2[tgt] ----
        __shared__ float a[RANKC];
        const int o = blockIdx.x;
        if (tid < RANKC)
            a[tid] = w1[((size_t)src_id[0] * NLANG_OUT + o) * RANKC + tid];
        __syncthreads();
        const int t = tgt_id[0];

        const int i0 = tid * 4;   // 256 threads * 4 = 1024
        float4 acc = *reinterpret_cast<const float4*>(weight + (size_t)o * Kdim + i0);
#pragma unroll
        for (int r = 0; r < RANKC; ++r) {
            const float4 b = *reinterpret_cast<const float4*>(w2 + ((size_t)t * RANKC + r) * Kdim + i0);
            const float ar = a[r];
            acc.x = fmaf(ar, b.x, acc.x);
            acc.y = fmaf(ar, b.y, acc.y);
            acc.z = fmaf(ar, b.z, acc.z);
            acc.w = fmaf(ar, b.w, acc.w);
        }
        __half2* p = reinterpret_cast<__half2*>(g_b + (size_t)o * Kdim + i0);
        p[0] = __floats2half2_rn(acc.x, acc.y);
        p[1] = __floats2half2_rn(acc.z, acc.w);
    } else {
        // ---- x cast: one float4 per thread ----
        const size_t i = (size_t)(blockIdx.x - Ndim) * blockDim.x + tid;  // < M*K/4
        const float4 v = x4[i];
        __half2* p = reinterpret_cast<__half2*>(g_a + 4 * i);
        p[0] = __floats2half2_rn(v.x, v.y);
        p[1] = __floats2half2_rn(v.z, v.w);
    }
}

// ---------------------------------------------------------------------------
// GEMM: 128x128 CTA tile, 8 warps (4 M x 2 N), warp tile 32x64, BK=64,
// 3-stage cp.async pipeline (32 KB/stage), ldmatrix + mma.sync fp16
// ---------------------------------------------------------------------------
__global__ void __launch_bounds__(256, 2)
gemm_kernel(float* __restrict__ out, const float* __restrict__ bias) {
    extern __shared__ char smem[];
    const uint32_t smem_base = smem_to_u32(smem);
    const int tid  = threadIdx.x;
    const int lane = tid & 31;
    const int wid  = tid >> 5;
    const int warp_m = wid & 3;     // 4 warps in M -> 32 rows each
    const int warp_n = wid >> 2;    // 2 warps in N -> 64 cols each
    const int n0 = blockIdx.x * BN; // n fastest: W-panel reuse in L2
    const int m0 = blockIdx.y * BM;

    // ---- cp.async mapping: 4 chunks each for A and B per thread ----
    // chunk id cid = j*256 + tid, row = cid>>3, ch = cid&7.
    // For fixed j, 8 consecutive lanes cover one full 128B row (coalesced).
    // row(j) = row(0) + 32*j and ch is j-invariant -> dst(j) = dst(0) + j*4096.
    const int row0 = tid >> 3;
    const int ch0  = tid & 7;
    const uint32_t st0 = swz(row0, ch0);
    const __half* srcA0 = g_a + (size_t)(m0 + row0) * Kdim + ch0 * 8;
    const __half* srcB0 = g_b + (size_t)(n0 + row0) * Kdim + ch0 * 8;
    constexpr size_t JSTRIDE = (size_t)32 * Kdim;   // +32 rows per j

    // ---- ldmatrix smem offsets (constant across stages) ----
    const int g  = lane >> 3;
    const int lr = lane & 7;
    // A: row = warp_m*32 + mt*16 + (g&1)*8 + lr, chunk = kk*2 + (g>>1)
    //    offA[mt][kk] = offA0[kk] + mt*2048   (row&7 invariant under +16)
    uint32_t offA0[4];
#pragma unroll
    for (int kk = 0; kk < 4; ++kk) {
        const int row = warp_m * 32 + (g & 1) * 8 + lr;
        offA0[kk] = swz(row, kk * 2 + (g >> 1));
    }
    // B: row = warp_n*64 + np*16 + (g>>1)*8 + lr, chunk = kk*2 + (g&1)
    //    offB[np][kk] = offB0[kk] + np*2048
    uint32_t offB0[4];
#pragma unroll
    for (int kk = 0; kk < 4; ++kk) {
        const int row = warp_n * 64 + (g >> 1) * 8 + lr;
        offB0[kk] = swz(row, kk * 2 + (g & 1));
    }

    float acc[2][8][4];
#pragma unroll
    for (int mt = 0; mt < 2; ++mt)
#pragma unroll
        for (int nt = 0; nt < 8; ++nt)
#pragma unroll
            for (int c = 0; c < 4; ++c) acc[mt][nt][c] = 0.f;

    // ---- prologue: stages 0..STAGES-2 ----
#pragma unroll
    for (int s = 0; s < STAGES - 1; ++s) {
        const uint32_t sa = smem_base + s * STAGE_BYTES;
        const uint32_t sb = sa + TILE_BYTES;
        const int k0 = s * BK;
#pragma unroll
        for (int j = 0; j < 4; ++j) {
            cp_async16(sa + st0 + j * 4096, srcA0 + j * JSTRIDE + k0);
            cp_async16(sb + st0 + j * 4096, srcB0 + j * JSTRIDE + k0);
        }
        cp_commit();
    }

    // ---- mainloop: 16 stages ----
    int ld_stage = STAGES - 1;
    int cp_stage = 0;
#pragma unroll 1
    for (int s = 0; s < KT; ++s) {
        cp_wait<STAGES - 2>();
        __syncthreads();

        // prefetch stage s+STAGES-1
        if (s + STAGES - 1 < KT) {
            const uint32_t sa = smem_base + ld_stage * STAGE_BYTES;
            const uint32_t sb = sa + TILE_BYTES;
            const int k0 = (s + STAGES - 1) * BK;
#pragma unroll
            for (int j = 0; j < 4; ++j) {
                cp_async16(sa + st0 + j * 4096, srcA0 + j * JSTRIDE + k0);
                cp_async16(sb + st0 + j * 4096, srcB0 + j * JSTRIDE + k0);
            }
        }
        cp_commit();   // commit every iter (possibly empty): fixed group count
        if (++ld_stage == STAGES) ld_stage = 0;

        const uint32_t sa = smem_base + cp_stage * STAGE_BYTES;
        const uint32_t sb = sa + TILE_BYTES;
        if (++cp_stage == STAGES) cp_stage = 0;

#pragma unroll
        for (int kk = 0; kk < 4; ++kk) {
            uint32_t a[2][4];
#pragma unroll
            for (int mt = 0; mt < 2; ++mt)
                ldsm_x4(a[mt][0], a[mt][1], a[mt][2], a[mt][3],
                        sa + offA0[kk] + mt * 2048);
            uint32_t b[8][2];
#pragma unroll
            for (int np = 0; np < 4; ++np) {
                uint32_t r0, r1, r2, r3;
                ldsm_x4(r0, r1, r2, r3, sb + offB0[kk] + np * 2048);
                b[2 * np][0] = r0; b[2 * np][1] = r1;
                b[2 * np + 1][0] = r2; b[2 * np + 1][1] = r3;
            }
#pragma unroll
            for (int mt = 0; mt < 2; ++mt)
#pragma unroll
                for (int nt = 0; nt < 8; ++nt)
                    mma_f16(acc[mt][nt][0], acc[mt][nt][1], acc[mt][nt][2], acc[mt][nt][3],
                            a[mt][0], a[mt][1], a[mt][2], a[mt][3],
                            b[nt][0], b[nt][1]);
        }
    }

    // ---- epilogue ----
    const int qid = lane >> 2;     // row 0..7 within m8
    const int qln = lane & 3;      // col pair
    const int nbase = n0 + warp_n * 64;
    float2 bv[8];
#pragma unroll
    for (int nt = 0; nt < 8; ++nt)
        bv[nt] = *reinterpret_cast<const float2*>(bias + nbase + nt * 8 + qln * 2);

#pragma unroll
    for (int mt = 0; mt < 2; ++mt) {
#pragma unroll
        for (int rr = 0; rr < 2; ++rr) {
            const int m = m0 + warp_m * 32 + mt * 16 + rr * 8 + qid;
            float* orow = out + (size_t)m * Ndim + nbase;
#pragma unroll
            for (int nt = 0; nt < 8; ++nt) {
                float2 v;
                v.x = acc[mt][nt][rr * 2 + 0] + bv[nt].x;
                v.y = acc[mt][nt][rr * 2 + 1] + bv[nt].y;
                *reinterpret_cast<float2*>(orow + nt * 8 + qln * 2) = v;
            }
        }
    }
}

// ---------------------------------------------------------------------------
// Launch
// ---------------------------------------------------------------------------
extern "C" void kernel_launch(void* const* d_in, const int* in_sizes, int n_in,
                              void* d_out, int out_size) {
    const float* x      = (const float*)d_in[0];   // [4,4096,1024]
    const float* weight = (const float*)d_in[1];   // [4096,1024]
    const float* bias   = (const float*)d_in[2];   // [4096]
    const float* w1     = (const float*)d_in[3];   // [9,4096,32]
    const float* w2     = (const float*)d_in[4];   // [9,32,1024]
    const int*   src_id = (const int*)d_in[5];
    const int*   tgt_id = (const int*)d_in[6];
    float* out = (float*)d_out;
    (void)in_sizes; (void)n_in; (void)out_size;

    cudaFuncSetAttribute(gemm_kernel, cudaFuncAttributeMaxDynamicSharedMemorySize, SMEM_BYTES);

    // Fused prep: 4096 w-blocks + 16384 x-blocks in one launch (overlapped).
    prep_kernel<<<Ndim + (Mdim * Kdim / 4) / 256, 256>>>(
        reinterpret_cast<const float4*>(x), weight, w1, w2, src_id, tgt_id);

    dim3 grid(Ndim / BN, Mdim / BM);   // (32, 128), n fastest
    gemm_kernel<<<grid, 256, SMEM_BYTES>>>(out, bias);
}